// round 16
// baseline (speedup 1.0000x reference)
#include <cuda_runtime.h>
#include <math.h>
#include <float.h>

// Fixed problem shape: img (16,3,512,512) f32, sbin=4 -> out (16,31,128,128) f32
#define BATCH 16
#define NCH   3
#define IH    512
#define IW    512
#define BH    128
#define BW    128

#define TS     16         // cells per tile side
#define WROWS  68         // pixel rows in window
#define MP     72         // smem pitch (u32): 16B-aligned strip stores
#define NSTRIP 18         // 4-px strips per row

#define HIST_ELEMS (BATCH * 18 * BH * BW)
#define NORM_ELEMS (BATCH * BH * BW)

__device__ float g_hist[HIST_ELEMS];
__device__ float g_norm[NORM_ELEMS];

// ---------------------------------------------------------------------------
// Kernel 1: gradients + orientation + per-cell gather + norm.
// Orientation argmax over D = [d0..d8, -d0..-d8] via TIE-EXACT adjacency bits:
//   bit k   (k=0..7) : d_k     >= d_{k+1}        (D_k >= D_{k+1})
//   bit 8            : d_8     >= -d_0           (D_8 >= D_9)
//   bit 9+m (m=0..7) : d_{m+1} >= d_m            (== -d_m >= -d_{m+1})
//   bit 17           : !bit8  (strict -d_8 > d_0, so (17,0) tie -> index 0)
//   bin = ffs(full & ~rot1(full)) - 1  == reference first-occurrence argmax
// ---------------------------------------------------------------------------
__global__ __launch_bounds__(256, 3) void hog_gather(const float* __restrict__ img) {
    __shared__ unsigned int s_pack[WROWS * MP];   // 19584 B
    __shared__ float        s_bins[18 * 256];     // 18432 B  (total 38016 B)

    const int tid = threadIdx.x;
    const int cx0 = blockIdx.x * TS;
    const int cy0 = blockIdx.y * TS;
    const int b   = blockIdx.z;

    const int y0  = 4 * cy0 - 2;        // image row of window row 0
    const int x0a = 4 * cx0 - 4;        // image col of smem col 0 (aligned)

    const float* base = img + (size_t)b * NCH * IH * IW;

    const float UU[9] = {1.0f, 0.9397f, 0.766f, 0.5f, 0.1736f,
                         -0.1736f, -0.5f, -0.766f, -0.9397f};
    const float VV[9] = {0.0f, 0.342f, 0.6428f, 0.866f, 0.9848f,
                         0.9848f, 0.866f, 0.6428f, 0.342f};

    // ---- zero per-thread bins (owner-only; sync below covers it) ----
#pragma unroll
    for (int o = 0; o < 18; o++) s_bins[o * 256 + tid] = 0.0f;

    // ---- Stage 1: per-pixel gradient / orientation, 4-px aligned strips ----
    for (int t = tid; t < NSTRIP * WROWS; t += 256) {
        const int s  = t % NSTRIP;
        const int py = t / NSTRIP;
        const int y  = y0 + py;
        const int xb = x0a + 4 * s;

        uint4 pk = make_uint4(0u, 0u, 0u, 0u);

        if (y >= 1 && y <= IH - 2 && xb >= 0 && xb <= IW - 4) {
            float bestv[4] = {-1.f, -1.f, -1.f, -1.f};
            float bdx[4], bdy[4];
#pragma unroll
            for (int c = 0; c < NCH; c++) {
                const float* rp = base + (size_t)c * IH * IW + (size_t)y * IW + xb;
                float4 up = *reinterpret_cast<const float4*>(rp - IW);
                float4 dn = *reinterpret_cast<const float4*>(rp + IW);
                float4 md = *reinterpret_cast<const float4*>(rp);
                float  lf = (xb > 0) ? rp[-1] : 0.f;
                float  rt = (xb + 4 <= IW - 1) ? rp[4] : 0.f;
                float mx[6] = {lf, md.x, md.y, md.z, md.w, rt};
                float u[4]  = {up.x, up.y, up.z, up.w};
                float d[4]  = {dn.x, dn.y, dn.z, dn.w};
#pragma unroll
                for (int i = 0; i < 4; i++) {
                    float gdy = d[i] - u[i];
                    float gdx = mx[i + 2] - mx[i];
                    float v = gdx * gdx + gdy * gdy;
                    if (v > bestv[i]) { bestv[i] = v; bdx[i] = gdx; bdy[i] = gdy; }
                }
            }
            unsigned int pka[4];
#pragma unroll
            for (int i = 0; i < 4; i++) {
                const float gdx = bdx[i];
                const float gdy = bdy[i];

                // the 9 dots, computed once; all decisions compare THESE values
                float d[9];
#pragma unroll
                for (int k = 0; k < 9; k++) d[k] = UU[k] * gdx + VV[k] * gdy;

                unsigned int fwd = 0u, rev = 0u;
#pragma unroll
                for (int k = 0; k < 8; k++) {
                    if (d[k] >= d[k + 1]) fwd |= (1u << k);       // bits 0..7
                    if (d[k + 1] >= d[k]) rev |= (1u << k);       // bits 9..16
                }
                const bool b8 = (d[8] >= -d[0]);

                unsigned int full = fwd | (rev << 9)
                                  | (b8 ? 0x100u : 0x20000u);     // bit8 / bit17
                unsigned int prev = ((full << 1) | (full >> 17)) & 0x3FFFFu;
                unsigned int mbit = full & ~prev;                 // local maxima
                int bo = __ffs(mbit) - 1;

                float vm = bestv[i];
                float mag = (vm > 0.f) ? vm * rsqrtf(vm) : 0.f;
                int x = xb + i;
                if (x < 1 || x > IW - 2) mag = 0.f;
                pka[i] = (__float_as_uint(mag) & 0xFFFFFFE0u) | (unsigned)bo;
            }
            pk = make_uint4(pka[0], pka[1], pka[2], pka[3]);
        }
        *reinterpret_cast<uint4*>(&s_pack[py * MP + 4 * s]) = pk;
    }

    __syncthreads();

    // ---- Stage 3: gather 8x8 footprint per cell (1 thread = 1 cell) ----
    const int lcy = tid >> 4;
    const int lcx = tid & 15;
    const int pr  = 4 * lcy;
    const int pc  = 4 * lcx;

    const float W8[8] = {0.125f, 0.375f, 0.625f, 0.875f,
                         0.875f, 0.625f, 0.375f, 0.125f};

#pragma unroll
    for (int dy = 0; dy < 8; dy++) {
        const float wy = W8[dy];
        const unsigned int* rowp = &s_pack[(pr + dy) * MP + pc];
        uint4 p0 = *reinterpret_cast<const uint4*>(rowp);
        uint4 p1 = *reinterpret_cast<const uint4*>(rowp + 4);
        uint4 p2 = *reinterpret_cast<const uint4*>(rowp + 8);
        unsigned int v[12] = {p0.x, p0.y, p0.z, p0.w,
                              p1.x, p1.y, p1.z, p1.w,
                              p2.x, p2.y, p2.z, p2.w};
#pragma unroll
        for (int dx = 0; dx < 8; dx++) {
            unsigned int u = v[dx + 2];
            float m = __uint_as_float(u & 0xFFFFFFE0u);
            int o = (int)(u & 31u);
            s_bins[o * 256 + tid] += m * (wy * W8[dx]);
        }
    }

    // ---- Stage 4: write hist + norm (coalesced stores) ----
    const int cy = cy0 + lcy;
    const int cx = cx0 + lcx;
    float* hb = g_hist + ((size_t)b * 18) * (BH * BW) + cy * BW + cx;

    float acc = 0.0f;
#pragma unroll
    for (int o = 0; o < 9; o++) {
        float a = s_bins[o * 256 + tid];
        float c = s_bins[(o + 9) * 256 + tid];
        hb[o * (BH * BW)]       = a;
        hb[(o + 9) * (BH * BW)] = c;
        float s = a + c;
        acc += s * s;
    }
    g_norm[(size_t)b * BH * BW + cy * BW + cx] = acc;
}

// ---------------------------------------------------------------------------
// Kernel 2: block-normalized features, 1 px/thread, fused o-loop (R10 best).
// ---------------------------------------------------------------------------
__global__ __launch_bounds__(256) void hog_feat(float* __restrict__ out) {
    int idx = blockIdx.x * blockDim.x + threadIdx.x;
    if (idx >= BATCH * BH * BW) return;
    int j = idx & (BW - 1);
    int t = idx >> 7;
    int i = t & (BH - 1);
    int b = t >> 7;

    float* ob = out + (size_t)b * 31 * BH * BW + i * BW + j;

    if (i == 0 || i == BH - 1 || j == 0 || j == BW - 1) {
#pragma unroll
        for (int ch = 0; ch < 31; ch++) ob[ch * (BH * BW)] = 0.0f;
        return;
    }

    const float* hb = g_hist + (size_t)b * 18 * BH * BW + i * BW + j;
    float src[18];
#pragma unroll
    for (int o = 0; o < 18; o++) src[o] = hb[o * (BH * BW)];

    const float* nb = g_norm + (size_t)b * BH * BW;
    float m[3][3];
#pragma unroll
    for (int r = 0; r < 3; r++)
#pragma unroll
        for (int c = 0; c < 3; c++)
            m[r][c] = nb[(i - 1 + r) * BW + (j - 1 + c)];

    const float EPS = 0.0001f;
    float n1 = rsqrtf(m[1][1] + m[2][1] + m[1][2] + m[2][2] + EPS);
    float n2 = rsqrtf(m[0][1] + m[1][1] + m[0][2] + m[1][2] + EPS);
    float n3 = rsqrtf(m[1][0] + m[2][0] + m[1][1] + m[2][1] + EPS);
    float n4 = rsqrtf(m[0][0] + m[1][0] + m[0][1] + m[1][1] + EPS);

    float t1 = 0.f, t2 = 0.f, t3 = 0.f, t4 = 0.f;
#pragma unroll
    for (int o = 0; o < 9; o++) {
        float a = src[o];
        float c = src[o + 9];

        float a1 = fminf(a * n1, 0.2f);
        float a2 = fminf(a * n2, 0.2f);
        float a3 = fminf(a * n3, 0.2f);
        float a4 = fminf(a * n4, 0.2f);
        float c1 = fminf(c * n1, 0.2f);
        float c2 = fminf(c * n2, 0.2f);
        float c3 = fminf(c * n3, 0.2f);
        float c4 = fminf(c * n4, 0.2f);

        ob[o * (BH * BW)]       = 0.5f * (a1 + a2 + a3 + a4);
        ob[(o + 9) * (BH * BW)] = 0.5f * (c1 + c2 + c3 + c4);

        float ss = a + c;
        float v = fminf(ss * n1, 0.2f) + fminf(ss * n2, 0.2f) +
                  fminf(ss * n3, 0.2f) + fminf(ss * n4, 0.2f);
        ob[(18 + o) * (BH * BW)] = 0.5f * v;

        t1 += a1 + c1;
        t2 += a2 + c2;
        t3 += a3 + c3;
        t4 += a4 + c4;
    }
    ob[27 * (BH * BW)] = 0.2357f * t1;
    ob[28 * (BH * BW)] = 0.2357f * t2;
    ob[29 * (BH * BW)] = 0.2357f * t3;
    ob[30 * (BH * BW)] = 0.2357f * t4;
}

// ---------------------------------------------------------------------------
extern "C" void kernel_launch(void* const* d_in, const int* in_sizes, int n_in,
                              void* d_out, int out_size) {
    const float* img = (const float*)d_in[0];
    float* out = (float*)d_out;

    dim3 grid(BW / TS, BH / TS, BATCH);   // (8, 8, 16)
    hog_gather<<<grid, 256>>>(img);

    int n = BATCH * BH * BW;
    hog_feat<<<(n + 255) / 256, 256>>>(out);
}

// round 17
// speedup vs baseline: 1.0238x; 1.0238x over previous
#include <cuda_runtime.h>
#include <math.h>
#include <float.h>

// Fixed problem shape: img (16,3,512,512) f32, sbin=4 -> out (16,31,128,128) f32
#define BATCH 16
#define NCH   3
#define IH    512
#define IW    512
#define BH    128
#define BW    128
#define PL    (BH * BW)

#define TS     16         // cells per tile side
#define WROWS  68         // pixel rows in window
#define MP     72         // smem pitch (u32): 16B-aligned strip stores
#define NSTRIP 18         // 4-px strips per row

__device__ float g_hist[BATCH * 18 * PL];
__device__ float g_norm[BATCH * PL];

// ---- packed f32x2 math (sm_103a) ----
#define MUL2(o_, a_, b_)    asm("mul.rn.f32x2 %0, %1, %2;" : "=l"(o_) : "l"(a_), "l"(b_))
#define ADD2(o_, a_, b_)    asm("add.rn.f32x2 %0, %1, %2;" : "=l"(o_) : "l"(a_), "l"(b_))
#define PACK2(o_, lo_, hi_) asm("mov.b64 %0, {%1, %2};" : "=l"(o_) : "f"(lo_), "f"(hi_))
#define UNPK2(lo_, hi_, i_) asm("mov.b64 {%0, %1}, %2;" : "=f"(lo_), "=f"(hi_) : "l"(i_))

// ---------------------------------------------------------------------------
// Exact orientation argmax (R10 form — fmax/fmin trees + eq-mask + ffs),
// operating on d computed EXACTLY as always: UU[k]*gdx + VV[k]*gdy.
// ---------------------------------------------------------------------------
__device__ __forceinline__ unsigned int orient_pack(float gdx, float gdy, float mag) {
    const float UU[9] = {1.0f, 0.9397f, 0.766f, 0.5f, 0.1736f,
                         -0.1736f, -0.5f, -0.766f, -0.9397f};
    const float VV[9] = {0.0f, 0.342f, 0.6428f, 0.866f, 0.9848f,
                         0.9848f, 0.866f, 0.6428f, 0.342f};
    float d[9];
#pragma unroll
    for (int k = 0; k < 9; k++) d[k] = UU[k] * gdx + VV[k] * gdy;

    float mx01 = fmaxf(d[0], d[1]), mx23 = fmaxf(d[2], d[3]);
    float mx45 = fmaxf(d[4], d[5]), mx67 = fmaxf(d[6], d[7]);
    float mxv = fmaxf(fmaxf(fmaxf(mx01, mx23), fmaxf(mx45, mx67)), d[8]);
    float mn01 = fminf(d[0], d[1]), mn23 = fminf(d[2], d[3]);
    float mn45 = fminf(d[4], d[5]), mn67 = fminf(d[6], d[7]);
    float mnv = fminf(fminf(fminf(mn01, mn23), fminf(mn45, mn67)), d[8]);

    bool pos = (mxv >= -mnv);            // positives first on exact tie
    float tgt = pos ? mxv : mnv;

    unsigned int mask = 0u;
#pragma unroll
    for (int k = 0; k < 9; k++)
        mask |= (d[k] == tgt) ? (1u << k) : 0u;
    int kk = __ffs(mask) - 1;            // first occurrence
    int bo = pos ? kk : kk + 9;

    return (__float_as_uint(mag) & 0xFFFFFFE0u) | (unsigned)bo;
}

// ---------------------------------------------------------------------------
// Kernel 1: gradients + orientation + per-cell gather + norm (R10 skeleton).
// Interior blocks (not touching image borders) take a guard-free fast path.
// ---------------------------------------------------------------------------
__global__ __launch_bounds__(256, 3) void hog_gather(const float* __restrict__ img) {
    __shared__ unsigned int s_pack[WROWS * MP];   // 19584 B
    __shared__ float        s_bins[18 * 256];     // 18432 B

    const int tid = threadIdx.x;
    const int cx0 = blockIdx.x * TS;
    const int cy0 = blockIdx.y * TS;
    const int b   = blockIdx.z;

    const int y0  = 4 * cy0 - 2;
    const int x0a = 4 * cx0 - 4;

    const bool interior = (blockIdx.x != 0) & (blockIdx.x != gridDim.x - 1) &
                          (blockIdx.y != 0) & (blockIdx.y != gridDim.y - 1);

    const float* base = img + (size_t)b * NCH * IH * IW;

#pragma unroll
    for (int o = 0; o < 18; o++) s_bins[o * 256 + tid] = 0.0f;

    // ---- Stage 1: per-pixel gradient / orientation, 4-px aligned strips ----
    for (int t = tid; t < NSTRIP * WROWS; t += 256) {
        const int s  = t % NSTRIP;
        const int py = t / NSTRIP;
        const int y  = y0 + py;
        const int xb = x0a + 4 * s;

        uint4 pk = make_uint4(0u, 0u, 0u, 0u);

        if (interior) {
            // guard-free: y in [62,449], xb in [60,448] — always valid
            float bestv[4] = {-1.f, -1.f, -1.f, -1.f};
            float bdx[4], bdy[4];
#pragma unroll
            for (int c = 0; c < NCH; c++) {
                const float* rp = base + (size_t)c * IH * IW + (size_t)y * IW + xb;
                float4 up = *reinterpret_cast<const float4*>(rp - IW);
                float4 dn = *reinterpret_cast<const float4*>(rp + IW);
                float4 md = *reinterpret_cast<const float4*>(rp);
                float  lf = rp[-1];
                float  rt = rp[4];
                float mx[6] = {lf, md.x, md.y, md.z, md.w, rt};
                float u[4]  = {up.x, up.y, up.z, up.w};
                float d[4]  = {dn.x, dn.y, dn.z, dn.w};
#pragma unroll
                for (int i = 0; i < 4; i++) {
                    float gdy = d[i] - u[i];
                    float gdx = mx[i + 2] - mx[i];
                    float v = gdx * gdx + gdy * gdy;
                    if (v > bestv[i]) { bestv[i] = v; bdx[i] = gdx; bdy[i] = gdy; }
                }
            }
            unsigned int pka[4];
#pragma unroll
            for (int i = 0; i < 4; i++) {
                float vm = bestv[i];
                float mag = vm * rsqrtf(fmaxf(vm, 1e-37f));   // exact for vm>=0
                pka[i] = orient_pack(bdx[i], bdy[i], mag);
            }
            pk = make_uint4(pka[0], pka[1], pka[2], pka[3]);
        } else if (y >= 1 && y <= IH - 2 && xb >= 0 && xb <= IW - 4) {
            float bestv[4] = {-1.f, -1.f, -1.f, -1.f};
            float bdx[4], bdy[4];
#pragma unroll
            for (int c = 0; c < NCH; c++) {
                const float* rp = base + (size_t)c * IH * IW + (size_t)y * IW + xb;
                float4 up = *reinterpret_cast<const float4*>(rp - IW);
                float4 dn = *reinterpret_cast<const float4*>(rp + IW);
                float4 md = *reinterpret_cast<const float4*>(rp);
                float  lf = (xb > 0) ? rp[-1] : 0.f;
                float  rt = (xb + 4 <= IW - 1) ? rp[4] : 0.f;
                float mx[6] = {lf, md.x, md.y, md.z, md.w, rt};
                float u[4]  = {up.x, up.y, up.z, up.w};
                float d[4]  = {dn.x, dn.y, dn.z, dn.w};
#pragma unroll
                for (int i = 0; i < 4; i++) {
                    float gdy = d[i] - u[i];
                    float gdx = mx[i + 2] - mx[i];
                    float v = gdx * gdx + gdy * gdy;
                    if (v > bestv[i]) { bestv[i] = v; bdx[i] = gdx; bdy[i] = gdy; }
                }
            }
            unsigned int pka[4];
#pragma unroll
            for (int i = 0; i < 4; i++) {
                float vm = bestv[i];
                float mag = (vm > 0.f) ? vm * rsqrtf(vm) : 0.f;
                int x = xb + i;
                if (x < 1 || x > IW - 2) mag = 0.f;
                pka[i] = orient_pack(bdx[i], bdy[i], mag);
            }
            pk = make_uint4(pka[0], pka[1], pka[2], pka[3]);
        }
        *reinterpret_cast<uint4*>(&s_pack[py * MP + 4 * s]) = pk;
    }

    __syncthreads();

    // ---- Stage 3: gather 8x8 footprint per cell (1 thread = 1 cell) ----
    const int lcy = tid >> 4;
    const int lcx = tid & 15;
    const int pr  = 4 * lcy;
    const int pc  = 4 * lcx;

    const float W8[8] = {0.125f, 0.375f, 0.625f, 0.875f,
                         0.875f, 0.625f, 0.375f, 0.125f};

#pragma unroll
    for (int dy = 0; dy < 8; dy++) {
        const float wy = W8[dy];
        const unsigned int* rowp = &s_pack[(pr + dy) * MP + pc];
        uint4 p0 = *reinterpret_cast<const uint4*>(rowp);
        uint4 p1 = *reinterpret_cast<const uint4*>(rowp + 4);
        uint4 p2 = *reinterpret_cast<const uint4*>(rowp + 8);
        unsigned int v[12] = {p0.x, p0.y, p0.z, p0.w,
                              p1.x, p1.y, p1.z, p1.w,
                              p2.x, p2.y, p2.z, p2.w};
#pragma unroll
        for (int dx = 0; dx < 8; dx++) {
            unsigned int u = v[dx + 2];
            float m = __uint_as_float(u & 0xFFFFFFE0u);
            int o = (int)(u & 31u);
            s_bins[o * 256 + tid] += m * (wy * W8[dx]);
        }
    }

    // ---- Stage 4: write hist + norm (coalesced stores) ----
    const int cy = cy0 + lcy;
    const int cx = cx0 + lcx;
    float* hb = g_hist + ((size_t)b * 18) * PL + cy * BW + cx;

    float acc = 0.0f;
#pragma unroll
    for (int o = 0; o < 9; o++) {
        float a = s_bins[o * 256 + tid];
        float c = s_bins[(o + 9) * 256 + tid];
        hb[o * PL]       = a;
        hb[(o + 9) * PL] = c;
        float s = a + c;
        acc += s * s;
    }
    g_norm[(size_t)b * PL + cy * BW + cx] = acc;
}

// ---------------------------------------------------------------------------
// Kernel 2: features, 2 px/thread, packed f32x2 muls/adds, float2 I/O.
// ---------------------------------------------------------------------------
__global__ __launch_bounds__(128) void hog_feat(float* __restrict__ out) {
    const int idx = blockIdx.x * 128 + threadIdx.x;   // 131072 total
    const int g = idx & 63;
    const int t = idx >> 6;
    const int i = t & 127;
    const int b = t >> 7;
    const int j = g << 1;

    float* ob = out + (size_t)b * 31 * PL + i * BW + j;

    if (i == 0 || i == BH - 1) {
        const float2 z = make_float2(0.f, 0.f);
#pragma unroll
        for (int ch = 0; ch < 31; ch++)
            *reinterpret_cast<float2*>(&ob[ch * PL]) = z;
        return;
    }

    const float h0  = (j == 0)   ? 0.f : 0.5f;       // px0 column-border mask
    const float h1  = (j == 126) ? 0.f : 0.5f;       // px1 (j+1==127) mask
    const float tm0 = (j == 0)   ? 0.f : 0.2357f;
    const float tm1 = (j == 126) ? 0.f : 0.2357f;

    // norm neighborhood: rows i-1..i+1, cols {j-1, j, j+1, j+2}
    const float* nb = g_norm + (size_t)b * PL;
    const int jm1 = (j >= 1) ? j - 1 : 0;
    const int jp2 = (j + 2 <= BW - 1) ? j + 2 : BW - 1;

    float r0[4], r1[4], r2[4];
    {
        const float* p = &nb[(i - 1) * BW];
        float2 v = *reinterpret_cast<const float2*>(&p[j]);
        r0[0] = p[jm1]; r0[1] = v.x; r0[2] = v.y; r0[3] = p[jp2];
    }
    {
        const float* p = &nb[i * BW];
        float2 v = *reinterpret_cast<const float2*>(&p[j]);
        r1[0] = p[jm1]; r1[1] = v.x; r1[2] = v.y; r1[3] = p[jp2];
    }
    {
        const float* p = &nb[(i + 1) * BW];
        float2 v = *reinterpret_cast<const float2*>(&p[j]);
        r2[0] = p[jm1]; r2[1] = v.x; r2[2] = v.y; r2[3] = p[jp2];
    }

    const float EPS = 0.0001f;
    float n1[2], n2[2], n3[2], n4[2];
#pragma unroll
    for (int e = 0; e < 2; e++) {
        n1[e] = rsqrtf(r1[e + 1] + r2[e + 1] + r1[e + 2] + r2[e + 2] + EPS);
        n2[e] = rsqrtf(r0[e + 1] + r1[e + 1] + r0[e + 2] + r1[e + 2] + EPS);
        n3[e] = rsqrtf(r1[e] + r2[e] + r1[e + 1] + r2[e + 1] + EPS);
        n4[e] = rsqrtf(r0[e] + r1[e] + r0[e + 1] + r1[e + 1] + EPS);
    }

    unsigned long long N1, N2, N3, N4;
    PACK2(N1, n1[0], n1[1]);
    PACK2(N2, n2[0], n2[1]);
    PACK2(N3, n3[0], n3[1]);
    PACK2(N4, n4[0], n4[1]);

    const float* hb = g_hist + (size_t)b * 18 * PL + i * BW + j;

    float t0a[4] = {0.f, 0.f, 0.f, 0.f};   // px0 texture sums per norm
    float t1a[4] = {0.f, 0.f, 0.f, 0.f};   // px1

#pragma unroll
    for (int o = 0; o < 9; o++) {
        unsigned long long A = *reinterpret_cast<const unsigned long long*>(&hb[o * PL]);
        unsigned long long C = *reinterpret_cast<const unsigned long long*>(&hb[(o + 9) * PL]);
        unsigned long long S;
        ADD2(S, A, C);

        unsigned long long PA[4], PC[4], PS[4];
        MUL2(PA[0], A, N1); MUL2(PA[1], A, N2); MUL2(PA[2], A, N3); MUL2(PA[3], A, N4);
        MUL2(PC[0], C, N1); MUL2(PC[1], C, N2); MUL2(PC[2], C, N3); MUL2(PC[3], C, N4);
        MUL2(PS[0], S, N1); MUL2(PS[1], S, N2); MUL2(PS[2], S, N3); MUL2(PS[3], S, N4);

        float al[4], ah[4], cl[4], ch2[4], sl[4], sh[4];
#pragma unroll
        for (int e = 0; e < 4; e++) {
            float x0, x1;
            UNPK2(x0, x1, PA[e]); al[e] = fminf(x0, 0.2f); ah[e] = fminf(x1, 0.2f);
            UNPK2(x0, x1, PC[e]); cl[e] = fminf(x0, 0.2f); ch2[e] = fminf(x1, 0.2f);
            UNPK2(x0, x1, PS[e]); sl[e] = fminf(x0, 0.2f); sh[e] = fminf(x1, 0.2f);
        }

        float ra0 = (al[0] + al[1]) + (al[2] + al[3]);
        float ra1 = (ah[0] + ah[1]) + (ah[2] + ah[3]);
        float rc0 = (cl[0] + cl[1]) + (cl[2] + cl[3]);
        float rc1 = (ch2[0] + ch2[1]) + (ch2[2] + ch2[3]);
        float rs0 = (sl[0] + sl[1]) + (sl[2] + sl[3]);
        float rs1 = (sh[0] + sh[1]) + (sh[2] + sh[3]);

#pragma unroll
        for (int e = 0; e < 4; e++) {
            t0a[e] += al[e] + cl[e];
            t1a[e] += ah[e] + ch2[e];
        }

        *reinterpret_cast<float2*>(&ob[o * PL])        = make_float2(ra0 * h0, ra1 * h1);
        *reinterpret_cast<float2*>(&ob[(o + 9) * PL])  = make_float2(rc0 * h0, rc1 * h1);
        *reinterpret_cast<float2*>(&ob[(18 + o) * PL]) = make_float2(rs0 * h0, rs1 * h1);
    }

    *reinterpret_cast<float2*>(&ob[27 * PL]) = make_float2(t0a[0] * tm0, t1a[0] * tm1);
    *reinterpret_cast<float2*>(&ob[28 * PL]) = make_float2(t0a[1] * tm0, t1a[1] * tm1);
    *reinterpret_cast<float2*>(&ob[29 * PL]) = make_float2(t0a[2] * tm0, t1a[2] * tm1);
    *reinterpret_cast<float2*>(&ob[30 * PL]) = make_float2(t0a[3] * tm0, t1a[3] * tm1);
}

// ---------------------------------------------------------------------------
extern "C" void kernel_launch(void* const* d_in, const int* in_sizes, int n_in,
                              void* d_out, int out_size) {
    const float* img = (const float*)d_in[0];
    float* out = (float*)d_out;

    dim3 grid(BW / TS, BH / TS, BATCH);   // (8, 8, 16)
    hog_gather<<<grid, 256>>>(img);

    hog_feat<<<1024, 128>>>(out);         // 131072 threads, 2 px each
}